// round 11
// baseline (speedup 1.0000x reference)
#include <cuda_runtime.h>
#include <cstdint>

#define NN 50000
#define EE 800000
#define FF 128
#define LL 3
#define GG 256
#define TT 10

// ---- scratch (device globals; no allocation allowed) ----
__device__ float g_agg[NN * FF];
__device__ float g_f1[NN * FF];
__device__ float g_f2[NN * FF];
__device__ float g_f3[NN * FF];
__device__ float g_W1T[LL * FF * FF];       // [384][128]
__device__ float g_Bhi[LL * FF * 2 * FF];   // [l][n=128][k=256] tf32-hi
__device__ float g_Blo[LL * FF * 2 * FF];   // tf32-lo
__device__ float g_pool[GG * LL * FF];
__device__ float g_z[GG * FF];
__device__ int   g_start[GG + 1];
__device__ int   g_src[EE];
__device__ int   g_dst[EE];
__device__ int   g_csr[EE];
__device__ int   g_rowptr[NN + 1];
__device__ int   g_indeg[NN];
__device__ int   g_cursor[NN];
__device__ int   g_idx64;

__device__ __forceinline__ float tf32_rn(float v) {
    uint32_t r; asm("cvt.rna.tf32.f32 %0, %1;" : "=r"(r) : "f"(v));
    return __uint_as_float(r);
}

// m16n8k8 tf32 MMA, D += A*B (row.col)
__device__ __forceinline__ void mma8(float4& d,
                                     uint32_t a0, uint32_t a1, uint32_t a2, uint32_t a3,
                                     uint32_t b0, uint32_t b1) {
    asm volatile(
        "mma.sync.aligned.m16n8k8.row.col.f32.tf32.tf32.f32 "
        "{%0,%1,%2,%3}, {%4,%5,%6,%7}, {%8,%9}, {%0,%1,%2,%3};"
        : "+f"(d.x), "+f"(d.y), "+f"(d.z), "+f"(d.w)
        : "r"(a0), "r"(a1), "r"(a2), "r"(a3), "r"(b0), "r"(b1));
}

// ================= preamble kernels =================
__global__ void gs_transposeW1_kernel(const float* __restrict__ W1) {
    int idx = blockIdx.x * blockDim.x + threadIdx.x;
    if (idx < LL * FF * FF) {
        int c = idx / (LL * FF), j = idx % (LL * FF);
        g_W1T[j * FF + c] = W1[idx];
    }
}

// split weights into tf32 hi/lo, concat Wl|Wr along K: B[l][n][k], k in [0,256)
__global__ void gs_prepB_kernel(const float* __restrict__ Wl,
                                const float* __restrict__ Wr) {
    int idx = blockIdx.x * blockDim.x + threadIdx.x;
    if (idx >= LL * FF * 2 * FF) return;
    int l = idx / (FF * 2 * FF), r = idx % (FF * 2 * FF);
    int n = r / (2 * FF), k = r % (2 * FF);
    float v = (k < FF) ? Wl[l * FF * FF + n * FF + k]
                       : Wr[l * FF * FF + n * FF + (k - FF)];
    float hi = tf32_rn(v);
    float lo = tf32_rn(v - hi);
    g_Bhi[idx] = hi;
    g_Blo[idx] = lo;
}

__global__ void gs_zero_idx_kernel() {
    int i = blockIdx.x * blockDim.x + threadIdx.x;
    if (i < NN) g_indeg[i] = 0;
}

__global__ void gs_detect_kernel(const int* __restrict__ ei32) {
    int is64 = 1;
    for (int i = 1; i < 256; i += 2)
        if (ei32[i] != 0) { is64 = 0; break; }
    g_idx64 = is64;
}

__global__ void gs_convert_count_kernel(const void* __restrict__ ei) {
    int e = blockIdx.x * blockDim.x + threadIdx.x;
    if (e >= EE) return;
    int s, d;
    if (g_idx64) {
        const long long* p = (const long long*)ei;
        s = (int)p[e]; d = (int)p[EE + e];
    } else {
        const int* p = (const int*)ei;
        s = p[e]; d = p[EE + e];
    }
    g_src[e] = s; g_dst[e] = d;
    atomicAdd(&g_indeg[d], 1);
}

__global__ void gs_scan_kernel() {
    __shared__ int ssum[1024];
    const int t = threadIdx.x;
    const int CH = (NN + 1023) / 1024;
    const int base = t * CH;
    int s = 0;
    for (int i = 0; i < CH; i++) {
        int idx = base + i;
        if (idx < NN) s += g_indeg[idx];
    }
    ssum[t] = s;
    __syncthreads();
    for (int off = 1; off < 1024; off <<= 1) {
        int v = (t >= off) ? ssum[t - off] : 0;
        __syncthreads();
        ssum[t] += v;
        __syncthreads();
    }
    int running = (t == 0) ? 0 : ssum[t - 1];
    for (int i = 0; i < CH; i++) {
        int idx = base + i;
        if (idx < NN) {
            g_rowptr[idx] = running;
            g_cursor[idx] = running;
            running += g_indeg[idx];
        }
    }
    if (t == 1023) g_rowptr[NN] = running;
}

__global__ void gs_fill_kernel() {
    int e = blockIdx.x * blockDim.x + threadIdx.x;
    if (e >= EE) return;
    int pos = atomicAdd(&g_cursor[g_dst[e]], 1);
    g_csr[pos] = g_src[e];
}

__global__ void gs_bounds_kernel(const void* __restrict__ batch) {
    int g = blockIdx.x * blockDim.x + threadIdx.x;
    if (g > GG) return;
    int is64 = g_idx64;
    const long long* b64 = (const long long*)batch;
    const int* b32 = (const int*)batch;
    int lo = 0, hi = NN;
    while (lo < hi) {
        int mid = (lo + hi) >> 1;
        long long v = is64 ? b64[mid] : (long long)b32[mid];
        if (v < (long long)g) lo = mid + 1; else hi = mid;
    }
    g_start[g] = lo;
}

// ---- gather-mean aggregation: one warp per dst node ----
__global__ void __launch_bounds__(256) gs_gather_kernel(const float* __restrict__ h) {
    int warp = (blockIdx.x * blockDim.x + threadIdx.x) >> 5;
    int lane = threadIdx.x & 31;
    if (warp >= NN) return;
    int s0 = g_rowptr[warp], s1 = g_rowptr[warp + 1];
    float4 acc = make_float4(0.f, 0.f, 0.f, 0.f);
    int j = s0;
    for (; j + 4 <= s1; j += 4) {
        int a = g_csr[j], b = g_csr[j + 1], c = g_csr[j + 2], d = g_csr[j + 3];
        float4 v0 = reinterpret_cast<const float4*>(h + (size_t)a * FF)[lane];
        float4 v1 = reinterpret_cast<const float4*>(h + (size_t)b * FF)[lane];
        float4 v2 = reinterpret_cast<const float4*>(h + (size_t)c * FF)[lane];
        float4 v3 = reinterpret_cast<const float4*>(h + (size_t)d * FF)[lane];
        acc.x += (v0.x + v1.x) + (v2.x + v3.x);
        acc.y += (v0.y + v1.y) + (v2.y + v3.y);
        acc.z += (v0.z + v1.z) + (v2.z + v3.z);
        acc.w += (v0.w + v1.w) + (v2.w + v3.w);
    }
    for (; j < s1; j++) {
        int s = g_csr[j];
        float4 v = reinterpret_cast<const float4*>(h + (size_t)s * FF)[lane];
        acc.x += v.x; acc.y += v.y; acc.z += v.z; acc.w += v.w;
    }
    float iv = (s1 > s0) ? 1.f / (float)(s1 - s0) : 0.f;
    acc.x *= iv; acc.y *= iv; acc.z *= iv; acc.w *= iv;
    reinterpret_cast<float4*>(g_agg + (size_t)warp * FF)[lane] = acc;
}

// ================= split-TF32 layer GEMM via mma.sync =================
// C[128 x 128] = [agg|hin](128 x 256) @ B(256k x 128n)^T + bias
// 512 threads, warp grid 4(m) x 4(n), warp tile 32x32, K chunks of 32.
#define APITCH33 33
#define SM_A_HI 0
#define SM_A_LO (128 * APITCH33)
#define SM_B_HI (2 * 128 * APITCH33)
#define SM_B_LO (3 * 128 * APITCH33)
#define SM_FLOATS (4 * 128 * APITCH33)

__global__ void __launch_bounds__(512) gs_gemm_mma_kernel(
    const float* __restrict__ hin,
    const float* __restrict__ Bhi, const float* __restrict__ Blo,
    const float* __restrict__ blp, float* __restrict__ hout)
{
    extern __shared__ float sf[];
    const int t = threadIdx.x;
    const int wid = t >> 5, lane = t & 31;
    const int wm = wid >> 2, wn = wid & 3;       // 4x4 warp grid
    const int lr = lane >> 2, lc = lane & 3;     // fragment row/col ids
    const int row0 = blockIdx.x * 128;

    float4 acc[2][4];
#pragma unroll
    for (int i = 0; i < 2; i++)
#pragma unroll
        for (int j = 0; j < 4; j++) acc[i][j] = make_float4(0.f, 0.f, 0.f, 0.f);

    for (int ck = 0; ck < 8; ck++) {
        const int kc0 = ck * 32;
        const float* srcp; int koff;
        if (kc0 < FF) { srcp = g_agg; koff = kc0; }
        else          { srcp = hin;   koff = kc0 - FF; }
        __syncthreads();
        // stage A chunk (128 x 32), split hi/lo on the fly
        for (int i = t; i < 1024; i += 512) {
            int r = i >> 3, q = i & 7;
            int gr = row0 + r; if (gr >= NN) gr = NN - 1;
            float4 v = *reinterpret_cast<const float4*>(
                srcp + (size_t)gr * FF + koff + q * 4);
            int o = r * APITCH33 + q * 4;
            float h0 = tf32_rn(v.x), h1 = tf32_rn(v.y),
                  h2 = tf32_rn(v.z), h3 = tf32_rn(v.w);
            sf[SM_A_HI + o + 0] = h0; sf[SM_A_LO + o + 0] = tf32_rn(v.x - h0);
            sf[SM_A_HI + o + 1] = h1; sf[SM_A_LO + o + 1] = tf32_rn(v.y - h1);
            sf[SM_A_HI + o + 2] = h2; sf[SM_A_LO + o + 2] = tf32_rn(v.z - h2);
            sf[SM_A_HI + o + 3] = h3; sf[SM_A_LO + o + 3] = tf32_rn(v.w - h3);
        }
        // stage B chunk (128n x 32k), pre-split in gmem (L2-resident)
        for (int i = t; i < 1024; i += 512) {
            int n = i >> 3, q = i & 7;
            size_t gidx = (size_t)n * 256 + kc0 + q * 4;
            float4 hv = *reinterpret_cast<const float4*>(Bhi + gidx);
            float4 lv = *reinterpret_cast<const float4*>(Blo + gidx);
            int o = n * APITCH33 + q * 4;
            sf[SM_B_HI + o + 0] = hv.x; sf[SM_B_LO + o + 0] = lv.x;
            sf[SM_B_HI + o + 1] = hv.y; sf[SM_B_LO + o + 1] = lv.y;
            sf[SM_B_HI + o + 2] = hv.z; sf[SM_B_LO + o + 2] = lv.z;
            sf[SM_B_HI + o + 3] = hv.w; sf[SM_B_LO + o + 3] = lv.w;
        }
        __syncthreads();

#pragma unroll
        for (int k8 = 0; k8 < 4; k8++) {
            const int kb = k8 * 8;
            // B fragments: col(n) = lr, row(k) = lc / lc+4
            uint32_t bh0[4], bh1[4], bl0[4], bl1[4];
#pragma unroll
            for (int fn = 0; fn < 4; fn++) {
                int n = wn * 32 + fn * 8 + lr;
                int ob = n * APITCH33 + kb + lc;
                bh0[fn] = __float_as_uint(sf[SM_B_HI + ob]);
                bh1[fn] = __float_as_uint(sf[SM_B_HI + ob + 4]);
                bl0[fn] = __float_as_uint(sf[SM_B_LO + ob]);
                bl1[fn] = __float_as_uint(sf[SM_B_LO + ob + 4]);
            }
            // A fragments per m-tile, then 3-term MMAs
#pragma unroll
            for (int fm = 0; fm < 2; fm++) {
                int r = wm * 32 + fm * 16 + lr;
                int oa = r * APITCH33 + kb + lc;
                uint32_t ah0 = __float_as_uint(sf[SM_A_HI + oa]);
                uint32_t ah1 = __float_as_uint(sf[SM_A_HI + oa + 8 * APITCH33]);
                uint32_t ah2 = __float_as_uint(sf[SM_A_HI + oa + 4]);
                uint32_t ah3 = __float_as_uint(sf[SM_A_HI + oa + 8 * APITCH33 + 4]);
                uint32_t al0 = __float_as_uint(sf[SM_A_LO + oa]);
                uint32_t al1 = __float_as_uint(sf[SM_A_LO + oa + 8 * APITCH33]);
                uint32_t al2 = __float_as_uint(sf[SM_A_LO + oa + 4]);
                uint32_t al3 = __float_as_uint(sf[SM_A_LO + oa + 8 * APITCH33 + 4]);
#pragma unroll
                for (int fn = 0; fn < 4; fn++) {
                    mma8(acc[fm][fn], ah0, ah1, ah2, ah3, bh0[fn], bh1[fn]);
                    mma8(acc[fm][fn], al0, al1, al2, al3, bh0[fn], bh1[fn]);
                    mma8(acc[fm][fn], ah0, ah1, ah2, ah3, bl0[fn], bl1[fn]);
                }
            }
        }
    }

    // epilogue: bias add + store (c0,c1 -> row; c2,c3 -> row+8)
#pragma unroll
    for (int fm = 0; fm < 2; fm++) {
#pragma unroll
        for (int fn = 0; fn < 4; fn++) {
            int row = row0 + wm * 32 + fm * 16 + lr;
            int col = wn * 32 + fn * 8 + lc * 2;
            float b0 = blp[col], b1 = blp[col + 1];
            float4 d = acc[fm][fn];
            if (row < NN) {
                float2 o = make_float2(d.x + b0, d.y + b1);
                *reinterpret_cast<float2*>(hout + (size_t)row * FF + col) = o;
            }
            if (row + 8 < NN) {
                float2 o = make_float2(d.z + b0, d.w + b1);
                *reinterpret_cast<float2*>(hout + (size_t)(row + 8) * FF + col) = o;
            }
        }
    }
}

// ---- global max pool over each graph segment; one block per graph ----
__global__ void gs_pool_kernel() {
    int g = blockIdx.x;
    int s = g_start[g], e = g_start[g + 1];
    int t = threadIdx.x;            // 0..383
    int l = t >> 7, c = t & 127;
    const float* f = (l == 0) ? g_f1 : (l == 1) ? g_f2 : g_f3;
    float m = -3.402823466e38f;
    int i = s;
    for (; i + 4 <= e; i += 4) {
        float v0 = f[(size_t)(i + 0) * FF + c];
        float v1 = f[(size_t)(i + 1) * FF + c];
        float v2 = f[(size_t)(i + 2) * FF + c];
        float v3 = f[(size_t)(i + 3) * FF + c];
        m = fmaxf(m, fmaxf(fmaxf(v0, v1), fmaxf(v2, v3)));
    }
    for (; i < e; i++) m = fmaxf(m, f[(size_t)i * FF + c]);
    g_pool[g * (LL * FF) + t] = m;
}

__global__ void gs_mlp1_kernel(const float* __restrict__ b1) {
    __shared__ float sp[LL * FF];
    int g = blockIdx.x, t = threadIdx.x;
    for (int i = t; i < LL * FF; i += FF) sp[i] = g_pool[g * (LL * FF) + i];
    __syncthreads();
    float acc = b1[t];
#pragma unroll 8
    for (int j = 0; j < LL * FF; j++) acc += sp[j] * g_W1T[j * FF + t];
    g_z[g * FF + t] = fmaxf(acc, 0.f);
}

__global__ void gs_mlp2_kernel(const float* __restrict__ W2,
                               const float* __restrict__ b2,
                               float* __restrict__ out) {
    __shared__ float sz[FF];
    int g = blockIdx.x, t = threadIdx.x;
    sz[t] = g_z[g * FF + t];
    __syncthreads();
    if (t < TT) {
        float acc = b2[t];
#pragma unroll
        for (int c = 0; c < FF; c++) acc += sz[c] * W2[t * FF + c];
        out[g * TT + t] = acc;
    }
}

extern "C" void kernel_launch(void* const* d_in, const int* in_sizes, int n_in,
                              void* d_out, int out_size) {
    const float* x     = (const float*)d_in[0];
    const void*  ei    = d_in[1];
    const void*  batch = d_in[2];
    const float* Wl    = (const float*)d_in[3];
    const float* bl    = (const float*)d_in[4];
    const float* Wr    = (const float*)d_in[5];
    const float* W1    = (const float*)d_in[6];
    const float* b1    = (const float*)d_in[7];
    const float* W2    = (const float*)d_in[8];
    const float* b2    = (const float*)d_in[9];
    float* out = (float*)d_out;

    size_t smem = SM_FLOATS * sizeof(float);   // 67,584 B
    cudaFuncSetAttribute(gs_gemm_mma_kernel,
                         cudaFuncAttributeMaxDynamicSharedMemorySize, (int)smem);

    gs_transposeW1_kernel<<<(LL * FF * FF + 255) / 256, 256>>>(W1);
    gs_prepB_kernel<<<(LL * FF * 2 * FF + 255) / 256, 256>>>(Wl, Wr);
    gs_zero_idx_kernel<<<(NN + 255) / 256, 256>>>();
    gs_detect_kernel<<<1, 1>>>((const int*)ei);
    gs_convert_count_kernel<<<(EE + 255) / 256, 256>>>(ei);
    gs_scan_kernel<<<1, 1024>>>();
    gs_fill_kernel<<<(EE + 255) / 256, 256>>>();
    gs_bounds_kernel<<<1, GG + 1>>>(batch);

    void *p_f1, *p_f2, *p_f3, *p_bhi, *p_blo;
    cudaGetSymbolAddress(&p_f1, g_f1);
    cudaGetSymbolAddress(&p_f2, g_f2);
    cudaGetSymbolAddress(&p_f3, g_f3);
    cudaGetSymbolAddress(&p_bhi, g_Bhi);
    cudaGetSymbolAddress(&p_blo, g_Blo);
    float* fbuf_sel[3] = {(float*)p_f1, (float*)p_f2, (float*)p_f3};

    const float* hin = x;
    for (int l = 0; l < LL; l++) {
        gs_gather_kernel<<<(NN * 32 + 255) / 256, 256>>>(hin);
        gs_gemm_mma_kernel<<<(NN + 127) / 128, 512, smem>>>(
            hin,
            (const float*)p_bhi + (size_t)l * FF * 2 * FF,
            (const float*)p_blo + (size_t)l * FF * 2 * FF,
            bl + l * FF, fbuf_sel[l]);
        hin = fbuf_sel[l];
    }

    gs_pool_kernel<<<GG, LL * FF>>>();
    gs_mlp1_kernel<<<GG, FF>>>(b1);
    gs_mlp2_kernel<<<GG, FF>>>(W2, b2, out);
}